// round 14
// baseline (speedup 1.0000x reference)
#include <cuda_runtime.h>
#include <cuda_fp16.h>
#include <cstdint>

// ---------------------------------------------------------------------------
// GAT encoder, 3 layers. Round 14: fp16 feature storage for layers 0/1
// aggregation (halves the L2-bound gather traffic). Alpha dots + accumulation
// + layer 2 stay fp32. GEMM mainloop = round-10 proven version. CSR build on
// forked stream (round 13, 206us).
// ---------------------------------------------------------------------------

#define MAXN 50000
#define MAXE 800000
#define MAXET (MAXE + MAXN)

__device__ __align__(16) float g_feat[MAXN * 128];   // fp32 (layer 2) or fp16 (layers 0/1) rows
__device__ __align__(16) float g_in  [MAXN * 128];
__device__ __align__(16) float g_as  [MAXN * 4];
__device__ __align__(16) float g_ad  [MAXN * 4];
__device__ int g_src [MAXET];
__device__ int g_dst [MAXET];
__device__ int g_csrc[MAXET];
__device__ int g_cnt [MAXN];
__device__ int g_fill[MAXN];
__device__ int g_rowptr[MAXN + 1];
__device__ int g_bsum[64];
__device__ int g_is64;

// ---------------------------------------------------------------------------
__global__ void detect_k(const unsigned int* __restrict__ raw) {
    unsigned int o = 0;
#pragma unroll
    for (int j = 1; j < 128; j += 2) o |= raw[j];
    g_is64 = (o == 0u) ? 1 : 0;
}

__global__ void zero_k(int* __restrict__ cnt, int* __restrict__ fill, int N) {
    int i = blockIdx.x * blockDim.x + threadIdx.x;
    if (i < N) { cnt[i] = 0; fill[i] = 0; }
}

__global__ void decode_hist_k(const void* __restrict__ raw, int E, int ET,
                              int* __restrict__ src, int* __restrict__ dst,
                              int* __restrict__ cnt) {
    int e = blockIdx.x * blockDim.x + threadIdx.x;
    if (e >= ET) return;
    int s, d;
    if (e < E) {
        if (g_is64) {
            const long long* p = (const long long*)raw;
            s = (int)p[e];
            d = (int)p[E + e];
        } else {
            const int* p = (const int*)raw;
            s = p[e];
            d = p[E + e];
        }
    } else {
        s = d = e - E;
    }
    src[e] = s;
    dst[e] = d;
    atomicAdd(&cnt[d], 1);
}

__device__ __forceinline__ int warp_incl_scan(int v) {
    int lane = threadIdx.x & 31;
#pragma unroll
    for (int o = 1; o < 32; o <<= 1) {
        int t = __shfl_up_sync(0xffffffffu, v, o);
        if (lane >= o) v += t;
    }
    return v;
}

__global__ __launch_bounds__(1024) void scan1_k(const int* __restrict__ cnt,
                                                int* __restrict__ rowptr,
                                                int* __restrict__ bsum, int N) {
    __shared__ int wsum[32];
    int tid = threadIdx.x;
    int idx = blockIdx.x * 1024 + tid;
    int wid = tid >> 5, lane = tid & 31;
    int v = (idx < N) ? cnt[idx] : 0;
    int inc = warp_incl_scan(v);
    if (lane == 31) wsum[wid] = inc;
    __syncthreads();
    if (wid == 0) {
        int w = wsum[lane];
        wsum[lane] = warp_incl_scan(w);
    }
    __syncthreads();
    int off = (wid > 0) ? wsum[wid - 1] : 0;
    if (idx < N) rowptr[idx] = off + inc - v;
    if (tid == 1023) bsum[blockIdx.x] = off + inc;
}

__global__ void scan2_k(int* __restrict__ bsum, int nb, int* __restrict__ rowptr, int N) {
    __shared__ int sh[64];
    int tid = threadIdx.x;
    sh[tid] = (tid < nb) ? bsum[tid] : 0;
    __syncthreads();
    for (int o = 1; o < 64; o <<= 1) {
        int t = (tid >= o) ? sh[tid - o] : 0;
        __syncthreads();
        sh[tid] += t;
        __syncthreads();
    }
    if (tid < nb) bsum[tid] = (tid > 0) ? sh[tid - 1] : 0;
    if (tid == 0) rowptr[N] = sh[nb - 1];
}

__global__ void scan3_k(int* __restrict__ rowptr, const int* __restrict__ bsum, int N) {
    int idx = blockIdx.x * blockDim.x + threadIdx.x;
    if (idx < N) rowptr[idx] += bsum[idx >> 10];
}

__global__ void scatter_k(const int* __restrict__ src, const int* __restrict__ dst,
                          int ET, const int* __restrict__ rowptr,
                          int* __restrict__ fill, int* __restrict__ csrc) {
    int e = blockIdx.x * blockDim.x + threadIdx.x;
    if (e >= ET) return;
    int d = dst[e];
    int pos = rowptr[d] + atomicAdd(&fill[d], 1);
    csrc[pos] = src[e];
}

// ---------------------------------------------------------------------------
// tf32 helpers
// ---------------------------------------------------------------------------
__device__ __forceinline__ uint32_t f2tf(float f) {
    uint32_t u;
    asm("cvt.rna.tf32.f32 %0, %1;" : "=r"(u) : "f"(f));
    return u;
}

__device__ __forceinline__ void mma8(float4& d, const uint32_t* a, const uint32_t* b) {
    asm volatile(
        "mma.sync.aligned.m16n8k8.row.col.f32.tf32.tf32.f32 "
        "{%0,%1,%2,%3}, {%4,%5,%6,%7}, {%8,%9}, {%0,%1,%2,%3};"
        : "+f"(d.x), "+f"(d.y), "+f"(d.z), "+f"(d.w)
        : "r"(a[0]), "r"(a[1]), "r"(a[2]), "r"(a[3]), "r"(b[0]), "r"(b[1]));
}

// ---------------------------------------------------------------------------
// Tensor-core GEMM (round-10 mainloop, KC=64, in-loop 3-term tf32 split).
// HALFO: store O rows as fp16 (aggregation input for layers 0/1).
// ---------------------------------------------------------------------------
template <int NC, int HH, bool HALFO>
__global__ __launch_bounds__(256) void gemm_tc(const float* __restrict__ X,
                                               const float* __restrict__ W,
                                               void* __restrict__ Ov,
                                               const float* __restrict__ avs,
                                               const float* __restrict__ avd,
                                               float* __restrict__ os,
                                               float* __restrict__ od, int M) {
    constexpr int KC = 64;
    constexpr int XSS = 68;
    constexpr int WSS = NC + 4;
    constexpr int CGW = NC / 2;
    constexpr int NT  = CGW / 8;
    constexpr int LH  = (HH == 4) ? 2 : 1;

    extern __shared__ float smem[];
    float* Xs = smem;
    float* Ws = smem + 128 * XSS;

    int tid = threadIdx.x;
    int warp = tid >> 5, lane = tid & 31;
    int rg = warp >> 1, cg2 = warp & 1;
    int lr = lane >> 2, lc = lane & 3;
    int rowbase = blockIdx.x * 128;

    float4 acc[2][NT];
#pragma unroll
    for (int mt = 0; mt < 2; mt++)
#pragma unroll
        for (int nt = 0; nt < NT; nt++)
            acc[mt][nt] = make_float4(0.f, 0.f, 0.f, 0.f);

    for (int kb = 0; kb < 128; kb += KC) {
        __syncthreads();
#pragma unroll
        for (int i = 0; i < 8; i++) {
            int t = tid + i * 256;
            int row = t >> 4, q = t & 15;
            float4 v = make_float4(0.f, 0.f, 0.f, 0.f);
            if (rowbase + row < M)
                v = *reinterpret_cast<const float4*>(X + (size_t)(rowbase + row) * 128 + kb + q * 4);
            reinterpret_cast<float4*>(Xs + row * XSS)[q] = v;
        }
#pragma unroll
        for (int i = 0; i < (KC * NC / 4) / 256; i++) {
            int t = tid + i * 256;
            int k = t / (NC / 4), q = t % (NC / 4);
            float4 v = *reinterpret_cast<const float4*>(W + (size_t)(kb + k) * NC + q * 4);
            reinterpret_cast<float4*>(Ws + k * WSS)[q] = v;
        }
        __syncthreads();

#pragma unroll
        for (int kc = 0; kc < KC / 8; kc++) {
            uint32_t ah[2][4], al[2][4];
#pragma unroll
            for (int mt = 0; mt < 2; mt++) {
                const float* ab = Xs + (rg * 32 + mt * 16 + lr) * XSS + kc * 8 + lc;
                float f0 = ab[0];
                float f1 = ab[8 * XSS];
                float f2 = ab[4];
                float f3 = ab[8 * XSS + 4];
                ah[mt][0] = f2tf(f0); al[mt][0] = f2tf(f0 - __uint_as_float(ah[mt][0]));
                ah[mt][1] = f2tf(f1); al[mt][1] = f2tf(f1 - __uint_as_float(ah[mt][1]));
                ah[mt][2] = f2tf(f2); al[mt][2] = f2tf(f2 - __uint_as_float(ah[mt][2]));
                ah[mt][3] = f2tf(f3); al[mt][3] = f2tf(f3 - __uint_as_float(ah[mt][3]));
            }
#pragma unroll
            for (int nt = 0; nt < NT; nt++) {
                const float* bb = Ws + (kc * 8 + lc) * WSS + cg2 * CGW + nt * 8 + lr;
                float g0 = bb[0];
                float g1 = bb[4 * WSS];
                uint32_t bh[2], bl[2];
                bh[0] = f2tf(g0); bl[0] = f2tf(g0 - __uint_as_float(bh[0]));
                bh[1] = f2tf(g1); bl[1] = f2tf(g1 - __uint_as_float(bh[1]));
#pragma unroll
                for (int mt = 0; mt < 2; mt++) {
                    mma8(acc[mt][nt], ah[mt], bh);
                    mma8(acc[mt][nt], ah[mt], bl);
                    mma8(acc[mt][nt], al[mt], bh);
                }
            }
        }
    }

    float* Of = reinterpret_cast<float*>(Ov);
    __half* Oh = reinterpret_cast<__half*>(Ov);

    float sA[2][2][LH], sD[2][2][LH];
#pragma unroll
    for (int mt = 0; mt < 2; mt++)
#pragma unroll
        for (int rs = 0; rs < 2; rs++)
#pragma unroll
            for (int lh = 0; lh < LH; lh++) { sA[mt][rs][lh] = 0.f; sD[mt][rs][lh] = 0.f; }

#pragma unroll
    for (int mt = 0; mt < 2; mt++) {
        int r0 = rowbase + rg * 32 + mt * 16 + lr;
#pragma unroll
        for (int nt = 0; nt < NT; nt++) {
            int col = cg2 * CGW + nt * 8 + 2 * lc;
            float4 d = acc[mt][nt];
            float av0 = __ldg(avs + col), av1 = __ldg(avs + col + 1);
            float dv0 = __ldg(avd + col), dv1 = __ldg(avd + col + 1);
            int lh = (HH == 4) ? (nt / (NT / 2)) : 0;
            sA[mt][0][lh] += d.x * av0 + d.y * av1;
            sD[mt][0][lh] += d.x * dv0 + d.y * dv1;
            sA[mt][1][lh] += d.z * av0 + d.w * av1;
            sD[mt][1][lh] += d.z * dv0 + d.w * dv1;
            if (HALFO) {
                if (r0 < M)
                    *reinterpret_cast<__half2*>(Oh + (size_t)r0 * NC + col) = __floats2half2_rn(d.x, d.y);
                if (r0 + 8 < M)
                    *reinterpret_cast<__half2*>(Oh + (size_t)(r0 + 8) * NC + col) = __floats2half2_rn(d.z, d.w);
            } else {
                if (r0 < M)
                    *reinterpret_cast<float2*>(Of + (size_t)r0 * NC + col) = make_float2(d.x, d.y);
                if (r0 + 8 < M)
                    *reinterpret_cast<float2*>(Of + (size_t)(r0 + 8) * NC + col) = make_float2(d.z, d.w);
            }
        }
    }

#pragma unroll
    for (int mt = 0; mt < 2; mt++)
#pragma unroll
        for (int rs = 0; rs < 2; rs++)
#pragma unroll
            for (int lh = 0; lh < LH; lh++) {
                float a = sA[mt][rs][lh], d = sD[mt][rs][lh];
                a += __shfl_xor_sync(0xffffffffu, a, 1);
                a += __shfl_xor_sync(0xffffffffu, a, 2);
                d += __shfl_xor_sync(0xffffffffu, d, 1);
                d += __shfl_xor_sync(0xffffffffu, d, 2);
                sA[mt][rs][lh] = a; sD[mt][rs][lh] = d;
            }

    if (HH == 4) {
        if (lc == 0) {
#pragma unroll
            for (int mt = 0; mt < 2; mt++)
#pragma unroll
                for (int rs = 0; rs < 2; rs++) {
                    int row = rowbase + rg * 32 + mt * 16 + rs * 8 + lr;
                    if (row < M) {
#pragma unroll
                        for (int lh = 0; lh < LH; lh++) {
                            os[row * 4 + cg2 * 2 + lh] = sA[mt][rs][lh];
                            od[row * 4 + cg2 * 2 + lh] = sD[mt][rs][lh];
                        }
                    }
                }
        }
    } else {
        __syncthreads();
        float* sp = smem;
        float* dp = smem + 256;
        if (lc == 0) {
#pragma unroll
            for (int mt = 0; mt < 2; mt++)
#pragma unroll
                for (int rs = 0; rs < 2; rs++) {
                    int lrow = rg * 32 + mt * 16 + rs * 8 + lr;
                    sp[lrow * 2 + cg2] = sA[mt][rs][0];
                    dp[lrow * 2 + cg2] = sD[mt][rs][0];
                }
        }
        __syncthreads();
        if (tid < 128) {
            int row = rowbase + tid;
            if (row < M) {
                os[row] = sp[tid * 2] + sp[tid * 2 + 1];
                od[row] = dp[tid * 2] + dp[tid * 2 + 1];
            }
        }
    }
}

// ---------------------------------------------------------------------------
// CSR aggregation, single sweep, fp16 feature rows (layers 0/1, HC=128).
// Lane l handles cols [4l, 4l+4): one 8-byte load = 4 halves.
// ---------------------------------------------------------------------------
__global__ __launch_bounds__(256) void agg128h_k(const int* __restrict__ rowptr,
                                                 const int* __restrict__ csrc,
                                                 const __half* __restrict__ feat,
                                                 const float* __restrict__ as_,
                                                 const float* __restrict__ ad_,
                                                 const float* __restrict__ b,
                                                 float* __restrict__ out, int N) {
    int gt = blockIdx.x * blockDim.x + threadIdx.x;
    int n = gt >> 5;
    int lane = gt & 31;
    if (n >= N) return;
    int h = lane >> 3;
    float adv = __ldg(ad_ + n * 4 + h);
    int p0 = __ldg(rowptr + n), p1 = __ldg(rowptr + n + 1);

    float den = 0.f;
    float4 acc = make_float4(0.f, 0.f, 0.f, 0.f);
    const __half2* f2 = reinterpret_cast<const __half2*>(feat);
    for (int i = p0; i < p1; i++) {
        int s = __ldg(csrc + i);
        // 8B vector load: two half2 = cols [4*lane, 4*lane+4)
        __half2 ha = __ldg(f2 + (size_t)s * 64 + lane * 2);
        __half2 hb = __ldg(f2 + (size_t)s * 64 + lane * 2 + 1);
        float v = __ldg(as_ + s * 4 + h) + adv;
        v = v > 0.f ? v : 0.2f * v;
        float ex = __expf(v);
        float2 fa = __half22float2(ha);
        float2 fb = __half22float2(hb);
        den += ex;
        acc.x += ex * fa.x; acc.y += ex * fa.y;
        acc.z += ex * fb.x; acc.w += ex * fb.y;
    }

    float w = 1.f / (den + 1e-16f);
    float4 bb = *reinterpret_cast<const float4*>(b + lane * 4);
    float4 o;
    o.x = fmaxf(acc.x * w + bb.x, 0.f);
    o.y = fmaxf(acc.y * w + bb.y, 0.f);
    o.z = fmaxf(acc.z * w + bb.z, 0.f);
    o.w = fmaxf(acc.w * w + bb.w, 0.f);
    reinterpret_cast<float4*>(out)[(size_t)n * 32 + lane] = o;
}

// fp32 aggregation for final layer (HC=64), unchanged.
__global__ __launch_bounds__(256) void agg64_k(const int* __restrict__ rowptr,
                                               const int* __restrict__ csrc,
                                               const float* __restrict__ feat,
                                               const float* __restrict__ as_,
                                               const float* __restrict__ ad_,
                                               const float* __restrict__ b,
                                               float* __restrict__ out, int N) {
    int gt = blockIdx.x * blockDim.x + threadIdx.x;
    int n = gt >> 5;
    int lane = gt & 31;
    if (n >= N) return;
    float adv = __ldg(ad_ + n);
    int p0 = __ldg(rowptr + n), p1 = __ldg(rowptr + n + 1);

    float den = 0.f;
    float2 acc = make_float2(0.f, 0.f);
    for (int i = p0; i < p1; i++) {
        int s = __ldg(csrc + i);
        float2 f = __ldg(reinterpret_cast<const float2*>(feat) + (size_t)s * 32 + lane);
        float v = __ldg(as_ + s) + adv;
        v = v > 0.f ? v : 0.2f * v;
        float ex = __expf(v);
        den += ex;
        acc.x += ex * f.x; acc.y += ex * f.y;
    }

    float w = 1.f / (den + 1e-16f);
    float2 bb = *reinterpret_cast<const float2*>(b + lane * 2);
    float2 o;
    o.x = acc.x * w + bb.x;
    o.y = acc.y * w + bb.y;
    reinterpret_cast<float2*>(out)[(size_t)n * 32 + lane] = o;
}

// ---------------------------------------------------------------------------
extern "C" void kernel_launch(void* const* d_in, const int* in_sizes, int n_in,
                              void* d_out, int out_size) {
    const float* x   = (const float*)d_in[0];
    const void*  ei  = d_in[1];
    const float* W0  = (const float*)d_in[2];
    const float* as0 = (const float*)d_in[3];
    const float* ad0 = (const float*)d_in[4];
    const float* b0  = (const float*)d_in[5];
    const float* W1  = (const float*)d_in[6];
    const float* as1 = (const float*)d_in[7];
    const float* ad1 = (const float*)d_in[8];
    const float* b1  = (const float*)d_in[9];
    const float* W2  = (const float*)d_in[10];
    const float* as2 = (const float*)d_in[11];
    const float* ad2 = (const float*)d_in[12];
    const float* b2  = (const float*)d_in[13];
    float* out = (float*)d_out;

    int N = in_sizes[0] / 128;
    int E = in_sizes[1] / 2;
    int ET = E + N;

    float *feat, *inb, *asb, *adb;
    int *srcp, *dstp, *csrc, *cnt, *fill, *rowptr, *bsum;
    cudaGetSymbolAddress((void**)&feat,   g_feat);
    cudaGetSymbolAddress((void**)&inb,    g_in);
    cudaGetSymbolAddress((void**)&asb,    g_as);
    cudaGetSymbolAddress((void**)&adb,    g_ad);
    cudaGetSymbolAddress((void**)&srcp,   g_src);
    cudaGetSymbolAddress((void**)&dstp,   g_dst);
    cudaGetSymbolAddress((void**)&csrc,   g_csrc);
    cudaGetSymbolAddress((void**)&cnt,    g_cnt);
    cudaGetSymbolAddress((void**)&fill,   g_fill);
    cudaGetSymbolAddress((void**)&rowptr, g_rowptr);
    cudaGetSymbolAddress((void**)&bsum,   g_bsum);

    const int TB = 256;
    int gemmGrid = (N + 127) / 128;
    int aggGrid = ((long)N * 32 + TB - 1) / TB;
    int nchunk = (N + 1023) / 1024;

    const int SM128 = (128 * 68 + 64 * 132) * 4;   // 68608 B
    const int SM64  = (128 * 68 + 64 * 68) * 4;    // 52224 B
    cudaFuncSetAttribute(gemm_tc<128, 4, true>,  cudaFuncAttributeMaxDynamicSharedMemorySize, SM128);
    cudaFuncSetAttribute(gemm_tc<64, 1, false>,  cudaFuncAttributeMaxDynamicSharedMemorySize, SM64);

    static cudaStream_t s2 = nullptr;
    static cudaEvent_t evFork = nullptr, evJoin = nullptr;
    if (s2 == nullptr) {
        cudaStreamCreateWithFlags(&s2, cudaStreamNonBlocking);
        cudaEventCreateWithFlags(&evFork, cudaEventDisableTiming);
        cudaEventCreateWithFlags(&evJoin, cudaEventDisableTiming);
    }

    // ---- fork: CSR build on s2, concurrent with layer-0 GEMM ----
    cudaEventRecord(evFork, 0);
    cudaStreamWaitEvent(s2, evFork, 0);

    detect_k<<<1, 1, 0, s2>>>((const unsigned int*)ei);
    zero_k<<<(N + TB - 1) / TB, TB, 0, s2>>>(cnt, fill, N);
    decode_hist_k<<<(ET + TB - 1) / TB, TB, 0, s2>>>(ei, E, ET, srcp, dstp, cnt);
    scan1_k<<<nchunk, 1024, 0, s2>>>(cnt, rowptr, bsum, N);
    scan2_k<<<1, 64, 0, s2>>>(bsum, nchunk, rowptr, N);
    scan3_k<<<(N + TB - 1) / TB, TB, 0, s2>>>(rowptr, bsum, N);
    scatter_k<<<(ET + TB - 1) / TB, TB, 0, s2>>>(srcp, dstp, ET, rowptr, fill, csrc);
    cudaEventRecord(evJoin, s2);

    // ---------------- Layer 0 (GEMM overlaps CSR build; h stored fp16) ----------------
    gemm_tc<128, 4, true><<<gemmGrid, TB, SM128>>>(x, W0, feat, as0, ad0, asb, adb, N);
    cudaStreamWaitEvent(0, evJoin, 0);
    agg128h_k<<<aggGrid, TB>>>(rowptr, csrc, (const __half*)feat, asb, adb, b0, inb, N);

    // ---------------- Layer 1 (h stored fp16) ----------------
    gemm_tc<128, 4, true><<<gemmGrid, TB, SM128>>>(inb, W1, feat, as1, ad1, asb, adb, N);
    agg128h_k<<<aggGrid, TB>>>(rowptr, csrc, (const __half*)feat, asb, adb, b1, inb, N);

    // ---------------- Layer 2 (full fp32) ----------------
    gemm_tc<64, 1, false><<<gemmGrid, TB, SM64>>>(inb, W2, feat, as2, ad2, asb, adb, N);
    agg64_k<<<aggGrid, TB>>>(rowptr, csrc, feat, asb, adb, b2, out, N);
}

// round 15
// speedup vs baseline: 1.0159x; 1.0159x over previous
#include <cuda_runtime.h>
#include <cstdint>

// ---------------------------------------------------------------------------
// GAT encoder, 3 layers. Round 15: aggregation software-pipelined (batch-4
// index prefetch -> 4 independent gathers in flight; agg was shown latency-
// bound, not BW-bound, by the fp16 experiment). feat back to fp32 (fp16
// reverted: no gain, worse error). GEMM/CSR/stream-fork = round 13 (206us).
// ---------------------------------------------------------------------------

#define MAXN 50000
#define MAXE 800000
#define MAXET (MAXE + MAXN)

__device__ __align__(16) float g_feat[MAXN * 128];
__device__ __align__(16) float g_in  [MAXN * 128];
__device__ __align__(16) float g_as  [MAXN * 4];
__device__ __align__(16) float g_ad  [MAXN * 4];
__device__ int g_src [MAXET];
__device__ int g_dst [MAXET];
__device__ int g_csrc[MAXET];
__device__ int g_cnt [MAXN];
__device__ int g_fill[MAXN];
__device__ int g_rowptr[MAXN + 1];
__device__ int g_bsum[64];
__device__ int g_is64;

// ---------------------------------------------------------------------------
__global__ void detect_k(const unsigned int* __restrict__ raw) {
    unsigned int o = 0;
#pragma unroll
    for (int j = 1; j < 128; j += 2) o |= raw[j];
    g_is64 = (o == 0u) ? 1 : 0;
}

__global__ void zero_k(int* __restrict__ cnt, int* __restrict__ fill, int N) {
    int i = blockIdx.x * blockDim.x + threadIdx.x;
    if (i < N) { cnt[i] = 0; fill[i] = 0; }
}

__global__ void decode_hist_k(const void* __restrict__ raw, int E, int ET,
                              int* __restrict__ src, int* __restrict__ dst,
                              int* __restrict__ cnt) {
    int e = blockIdx.x * blockDim.x + threadIdx.x;
    if (e >= ET) return;
    int s, d;
    if (e < E) {
        if (g_is64) {
            const long long* p = (const long long*)raw;
            s = (int)p[e];
            d = (int)p[E + e];
        } else {
            const int* p = (const int*)raw;
            s = p[e];
            d = p[E + e];
        }
    } else {
        s = d = e - E;
    }
    src[e] = s;
    dst[e] = d;
    atomicAdd(&cnt[d], 1);
}

__device__ __forceinline__ int warp_incl_scan(int v) {
    int lane = threadIdx.x & 31;
#pragma unroll
    for (int o = 1; o < 32; o <<= 1) {
        int t = __shfl_up_sync(0xffffffffu, v, o);
        if (lane >= o) v += t;
    }
    return v;
}

__global__ __launch_bounds__(1024) void scan1_k(const int* __restrict__ cnt,
                                                int* __restrict__ rowptr,
                                                int* __restrict__ bsum, int N) {
    __shared__ int wsum[32];
    int tid = threadIdx.x;
    int idx = blockIdx.x * 1024 + tid;
    int wid = tid >> 5, lane = tid & 31;
    int v = (idx < N) ? cnt[idx] : 0;
    int inc = warp_incl_scan(v);
    if (lane == 31) wsum[wid] = inc;
    __syncthreads();
    if (wid == 0) {
        int w = wsum[lane];
        wsum[lane] = warp_incl_scan(w);
    }
    __syncthreads();
    int off = (wid > 0) ? wsum[wid - 1] : 0;
    if (idx < N) rowptr[idx] = off + inc - v;
    if (tid == 1023) bsum[blockIdx.x] = off + inc;
}

__global__ void scan2_k(int* __restrict__ bsum, int nb, int* __restrict__ rowptr, int N) {
    __shared__ int sh[64];
    int tid = threadIdx.x;
    sh[tid] = (tid < nb) ? bsum[tid] : 0;
    __syncthreads();
    for (int o = 1; o < 64; o <<= 1) {
        int t = (tid >= o) ? sh[tid - o] : 0;
        __syncthreads();
        sh[tid] += t;
        __syncthreads();
    }
    if (tid < nb) bsum[tid] = (tid > 0) ? sh[tid - 1] : 0;
    if (tid == 0) rowptr[N] = sh[nb - 1];
}

__global__ void scan3_k(int* __restrict__ rowptr, const int* __restrict__ bsum, int N) {
    int idx = blockIdx.x * blockDim.x + threadIdx.x;
    if (idx < N) rowptr[idx] += bsum[idx >> 10];
}

__global__ void scatter_k(const int* __restrict__ src, const int* __restrict__ dst,
                          int ET, const int* __restrict__ rowptr,
                          int* __restrict__ fill, int* __restrict__ csrc) {
    int e = blockIdx.x * blockDim.x + threadIdx.x;
    if (e >= ET) return;
    int d = dst[e];
    int pos = rowptr[d] + atomicAdd(&fill[d], 1);
    csrc[pos] = src[e];
}

// ---------------------------------------------------------------------------
// tf32 helpers
// ---------------------------------------------------------------------------
__device__ __forceinline__ uint32_t f2tf(float f) {
    uint32_t u;
    asm("cvt.rna.tf32.f32 %0, %1;" : "=r"(u) : "f"(f));
    return u;
}

__device__ __forceinline__ void mma8(float4& d, const uint32_t* a, const uint32_t* b) {
    asm volatile(
        "mma.sync.aligned.m16n8k8.row.col.f32.tf32.tf32.f32 "
        "{%0,%1,%2,%3}, {%4,%5,%6,%7}, {%8,%9}, {%0,%1,%2,%3};"
        : "+f"(d.x), "+f"(d.y), "+f"(d.z), "+f"(d.w)
        : "r"(a[0]), "r"(a[1]), "r"(a[2]), "r"(a[3]), "r"(b[0]), "r"(b[1]));
}

// ---------------------------------------------------------------------------
// Tensor-core GEMM (round-10 mainloop, KC=64, in-loop 3-term tf32 split).
// ---------------------------------------------------------------------------
template <int NC, int HH>
__global__ __launch_bounds__(256) void gemm_tc(const float* __restrict__ X,
                                               const float* __restrict__ W,
                                               float* __restrict__ O,
                                               const float* __restrict__ avs,
                                               const float* __restrict__ avd,
                                               float* __restrict__ os,
                                               float* __restrict__ od, int M) {
    constexpr int KC = 64;
    constexpr int XSS = 68;
    constexpr int WSS = NC + 4;
    constexpr int CGW = NC / 2;
    constexpr int NT  = CGW / 8;
    constexpr int LH  = (HH == 4) ? 2 : 1;

    extern __shared__ float smem[];
    float* Xs = smem;
    float* Ws = smem + 128 * XSS;

    int tid = threadIdx.x;
    int warp = tid >> 5, lane = tid & 31;
    int rg = warp >> 1, cg2 = warp & 1;
    int lr = lane >> 2, lc = lane & 3;
    int rowbase = blockIdx.x * 128;

    float4 acc[2][NT];
#pragma unroll
    for (int mt = 0; mt < 2; mt++)
#pragma unroll
        for (int nt = 0; nt < NT; nt++)
            acc[mt][nt] = make_float4(0.f, 0.f, 0.f, 0.f);

    for (int kb = 0; kb < 128; kb += KC) {
        __syncthreads();
#pragma unroll
        for (int i = 0; i < 8; i++) {
            int t = tid + i * 256;
            int row = t >> 4, q = t & 15;
            float4 v = make_float4(0.f, 0.f, 0.f, 0.f);
            if (rowbase + row < M)
                v = *reinterpret_cast<const float4*>(X + (size_t)(rowbase + row) * 128 + kb + q * 4);
            reinterpret_cast<float4*>(Xs + row * XSS)[q] = v;
        }
#pragma unroll
        for (int i = 0; i < (KC * NC / 4) / 256; i++) {
            int t = tid + i * 256;
            int k = t / (NC / 4), q = t % (NC / 4);
            float4 v = *reinterpret_cast<const float4*>(W + (size_t)(kb + k) * NC + q * 4);
            reinterpret_cast<float4*>(Ws + k * WSS)[q] = v;
        }
        __syncthreads();

#pragma unroll
        for (int kc = 0; kc < KC / 8; kc++) {
            uint32_t ah[2][4], al[2][4];
#pragma unroll
            for (int mt = 0; mt < 2; mt++) {
                const float* ab = Xs + (rg * 32 + mt * 16 + lr) * XSS + kc * 8 + lc;
                float f0 = ab[0];
                float f1 = ab[8 * XSS];
                float f2 = ab[4];
                float f3 = ab[8 * XSS + 4];
                ah[mt][0] = f2tf(f0); al[mt][0] = f2tf(f0 - __uint_as_float(ah[mt][0]));
                ah[mt][1] = f2tf(f1); al[mt][1] = f2tf(f1 - __uint_as_float(ah[mt][1]));
                ah[mt][2] = f2tf(f2); al[mt][2] = f2tf(f2 - __uint_as_float(ah[mt][2]));
                ah[mt][3] = f2tf(f3); al[mt][3] = f2tf(f3 - __uint_as_float(ah[mt][3]));
            }
#pragma unroll
            for (int nt = 0; nt < NT; nt++) {
                const float* bb = Ws + (kc * 8 + lc) * WSS + cg2 * CGW + nt * 8 + lr;
                float g0 = bb[0];
                float g1 = bb[4 * WSS];
                uint32_t bh[2], bl[2];
                bh[0] = f2tf(g0); bl[0] = f2tf(g0 - __uint_as_float(bh[0]));
                bh[1] = f2tf(g1); bl[1] = f2tf(g1 - __uint_as_float(bh[1]));
#pragma unroll
                for (int mt = 0; mt < 2; mt++) {
                    mma8(acc[mt][nt], ah[mt], bh);
                    mma8(acc[mt][nt], ah[mt], bl);
                    mma8(acc[mt][nt], al[mt], bh);
                }
            }
        }
    }

    float sA[2][2][LH], sD[2][2][LH];
#pragma unroll
    for (int mt = 0; mt < 2; mt++)
#pragma unroll
        for (int rs = 0; rs < 2; rs++)
#pragma unroll
            for (int lh = 0; lh < LH; lh++) { sA[mt][rs][lh] = 0.f; sD[mt][rs][lh] = 0.f; }

#pragma unroll
    for (int mt = 0; mt < 2; mt++) {
        int r0 = rowbase + rg * 32 + mt * 16 + lr;
#pragma unroll
        for (int nt = 0; nt < NT; nt++) {
            int col = cg2 * CGW + nt * 8 + 2 * lc;
            float4 d = acc[mt][nt];
            float av0 = __ldg(avs + col), av1 = __ldg(avs + col + 1);
            float dv0 = __ldg(avd + col), dv1 = __ldg(avd + col + 1);
            int lh = (HH == 4) ? (nt / (NT / 2)) : 0;
            sA[mt][0][lh] += d.x * av0 + d.y * av1;
            sD[mt][0][lh] += d.x * dv0 + d.y * dv1;
            sA[mt][1][lh] += d.z * av0 + d.w * av1;
            sD[mt][1][lh] += d.z * dv0 + d.w * dv1;
            if (r0 < M)
                *reinterpret_cast<float2*>(O + (size_t)r0 * NC + col) = make_float2(d.x, d.y);
            if (r0 + 8 < M)
                *reinterpret_cast<float2*>(O + (size_t)(r0 + 8) * NC + col) = make_float2(d.z, d.w);
        }
    }

#pragma unroll
    for (int mt = 0; mt < 2; mt++)
#pragma unroll
        for (int rs = 0; rs < 2; rs++)
#pragma unroll
            for (int lh = 0; lh < LH; lh++) {
                float a = sA[mt][rs][lh], d = sD[mt][rs][lh];
                a += __shfl_xor_sync(0xffffffffu, a, 1);
                a += __shfl_xor_sync(0xffffffffu, a, 2);
                d += __shfl_xor_sync(0xffffffffu, d, 1);
                d += __shfl_xor_sync(0xffffffffu, d, 2);
                sA[mt][rs][lh] = a; sD[mt][rs][lh] = d;
            }

    if (HH == 4) {
        if (lc == 0) {
#pragma unroll
            for (int mt = 0; mt < 2; mt++)
#pragma unroll
                for (int rs = 0; rs < 2; rs++) {
                    int row = rowbase + rg * 32 + mt * 16 + rs * 8 + lr;
                    if (row < M) {
#pragma unroll
                        for (int lh = 0; lh < LH; lh++) {
                            os[row * 4 + cg2 * 2 + lh] = sA[mt][rs][lh];
                            od[row * 4 + cg2 * 2 + lh] = sD[mt][rs][lh];
                        }
                    }
                }
        }
    } else {
        __syncthreads();
        float* sp = smem;
        float* dp = smem + 256;
        if (lc == 0) {
#pragma unroll
            for (int mt = 0; mt < 2; mt++)
#pragma unroll
                for (int rs = 0; rs < 2; rs++) {
                    int lrow = rg * 32 + mt * 16 + rs * 8 + lr;
                    sp[lrow * 2 + cg2] = sA[mt][rs][0];
                    dp[lrow * 2 + cg2] = sD[mt][rs][0];
                }
        }
        __syncthreads();
        if (tid < 128) {
            int row = rowbase + tid;
            if (row < M) {
                os[row] = sp[tid * 2] + sp[tid * 2 + 1];
                od[row] = dp[tid * 2] + dp[tid * 2 + 1];
            }
        }
    }
}

// ---------------------------------------------------------------------------
// CSR aggregation, batch-4 software pipelined (MLP=4 gathers in flight).
// HC=128: warp per node, lane = float4 slot, head h = lane>>3.
// ---------------------------------------------------------------------------
__global__ __launch_bounds__(256) void agg128_k(const int* __restrict__ rowptr,
                                                const int* __restrict__ csrc,
                                                const float* __restrict__ feat,
                                                const float* __restrict__ as_,
                                                const float* __restrict__ ad_,
                                                const float* __restrict__ b,
                                                float* __restrict__ out, int N) {
    int gt = blockIdx.x * blockDim.x + threadIdx.x;
    int n = gt >> 5;
    int lane = gt & 31;
    if (n >= N) return;
    int h = lane >> 3;
    float adv = __ldg(ad_ + n * 4 + h);
    int p0 = __ldg(rowptr + n), p1 = __ldg(rowptr + n + 1);

    float den = 0.f;
    float4 acc = make_float4(0.f, 0.f, 0.f, 0.f);
    const float4* f4 = reinterpret_cast<const float4*>(feat);

    int i = p0;
    for (; i + 4 <= p1; i += 4) {
        int s0 = __ldg(csrc + i);
        int s1 = __ldg(csrc + i + 1);
        int s2 = __ldg(csrc + i + 2);
        int s3 = __ldg(csrc + i + 3);
        // issue all gathers back-to-back (4 in flight)
        float4 f0 = __ldg(f4 + (size_t)s0 * 32 + lane);
        float4 f1 = __ldg(f4 + (size_t)s1 * 32 + lane);
        float4 f2 = __ldg(f4 + (size_t)s2 * 32 + lane);
        float4 f3 = __ldg(f4 + (size_t)s3 * 32 + lane);
        float a0 = __ldg(as_ + s0 * 4 + h);
        float a1 = __ldg(as_ + s1 * 4 + h);
        float a2 = __ldg(as_ + s2 * 4 + h);
        float a3 = __ldg(as_ + s3 * 4 + h);
        float v, ex;
        v = a0 + adv; v = v > 0.f ? v : 0.2f * v; ex = __expf(v);
        den += ex;
        acc.x += ex * f0.x; acc.y += ex * f0.y; acc.z += ex * f0.z; acc.w += ex * f0.w;
        v = a1 + adv; v = v > 0.f ? v : 0.2f * v; ex = __expf(v);
        den += ex;
        acc.x += ex * f1.x; acc.y += ex * f1.y; acc.z += ex * f1.z; acc.w += ex * f1.w;
        v = a2 + adv; v = v > 0.f ? v : 0.2f * v; ex = __expf(v);
        den += ex;
        acc.x += ex * f2.x; acc.y += ex * f2.y; acc.z += ex * f2.z; acc.w += ex * f2.w;
        v = a3 + adv; v = v > 0.f ? v : 0.2f * v; ex = __expf(v);
        den += ex;
        acc.x += ex * f3.x; acc.y += ex * f3.y; acc.z += ex * f3.z; acc.w += ex * f3.w;
    }
    for (; i < p1; i++) {
        int s = __ldg(csrc + i);
        float4 f = __ldg(f4 + (size_t)s * 32 + lane);
        float v = __ldg(as_ + s * 4 + h) + adv;
        v = v > 0.f ? v : 0.2f * v;
        float ex = __expf(v);
        den += ex;
        acc.x += ex * f.x; acc.y += ex * f.y; acc.z += ex * f.z; acc.w += ex * f.w;
    }

    float w = 1.f / (den + 1e-16f);
    float4 bb = *reinterpret_cast<const float4*>(b + lane * 4);
    float4 o;
    o.x = fmaxf(acc.x * w + bb.x, 0.f);
    o.y = fmaxf(acc.y * w + bb.y, 0.f);
    o.z = fmaxf(acc.z * w + bb.z, 0.f);
    o.w = fmaxf(acc.w * w + bb.w, 0.f);
    reinterpret_cast<float4*>(out)[(size_t)n * 32 + lane] = o;
}

// HC=64 final layer, batch-4 pipelined, float2 per lane.
__global__ __launch_bounds__(256) void agg64_k(const int* __restrict__ rowptr,
                                               const int* __restrict__ csrc,
                                               const float* __restrict__ feat,
                                               const float* __restrict__ as_,
                                               const float* __restrict__ ad_,
                                               const float* __restrict__ b,
                                               float* __restrict__ out, int N) {
    int gt = blockIdx.x * blockDim.x + threadIdx.x;
    int n = gt >> 5;
    int lane = gt & 31;
    if (n >= N) return;
    float adv = __ldg(ad_ + n);
    int p0 = __ldg(rowptr + n), p1 = __ldg(rowptr + n + 1);

    float den = 0.f;
    float2 acc = make_float2(0.f, 0.f);
    const float2* f2p = reinterpret_cast<const float2*>(feat);

    int i = p0;
    for (; i + 4 <= p1; i += 4) {
        int s0 = __ldg(csrc + i);
        int s1 = __ldg(csrc + i + 1);
        int s2 = __ldg(csrc + i + 2);
        int s3 = __ldg(csrc + i + 3);
        float2 f0 = __ldg(f2p + (size_t)s0 * 32 + lane);
        float2 f1 = __ldg(f2p + (size_t)s1 * 32 + lane);
        float2 f2 = __ldg(f2p + (size_t)s2 * 32 + lane);
        float2 f3 = __ldg(f2p + (size_t)s3 * 32 + lane);
        float a0 = __ldg(as_ + s0);
        float a1 = __ldg(as_ + s1);
        float a2 = __ldg(as_ + s2);
        float a3 = __ldg(as_ + s3);
        float v, ex;
        v = a0 + adv; v = v > 0.f ? v : 0.2f * v; ex = __expf(v);
        den += ex; acc.x += ex * f0.x; acc.y += ex * f0.y;
        v = a1 + adv; v = v > 0.f ? v : 0.2f * v; ex = __expf(v);
        den += ex; acc.x += ex * f1.x; acc.y += ex * f1.y;
        v = a2 + adv; v = v > 0.f ? v : 0.2f * v; ex = __expf(v);
        den += ex; acc.x += ex * f2.x; acc.y += ex * f2.y;
        v = a3 + adv; v = v > 0.f ? v : 0.2f * v; ex = __expf(v);
        den += ex; acc.x += ex * f3.x; acc.y += ex * f3.y;
    }
    for (; i < p1; i++) {
        int s = __ldg(csrc + i);
        float2 f = __ldg(f2p + (size_t)s * 32 + lane);
        float v = __ldg(as_ + s) + adv;
        v = v > 0.f ? v : 0.2f * v;
        float ex = __expf(v);
        den += ex; acc.x += ex * f.x; acc.y += ex * f.y;
    }

    float w = 1.f / (den + 1e-16f);
    float2 bb = *reinterpret_cast<const float2*>(b + lane * 2);
    float2 o;
    o.x = acc.x * w + bb.x;
    o.y = acc.y * w + bb.y;
    reinterpret_cast<float2*>(out)[(size_t)n * 32 + lane] = o;
}

// ---------------------------------------------------------------------------
extern "C" void kernel_launch(void* const* d_in, const int* in_sizes, int n_in,
                              void* d_out, int out_size) {
    const float* x   = (const float*)d_in[0];
    const void*  ei  = d_in[1];
    const float* W0  = (const float*)d_in[2];
    const float* as0 = (const float*)d_in[3];
    const float* ad0 = (const float*)d_in[4];
    const float* b0  = (const float*)d_in[5];
    const float* W1  = (const float*)d_in[6];
    const float* as1 = (const float*)d_in[7];
    const float* ad1 = (const float*)d_in[8];
    const float* b1  = (const float*)d_in[9];
    const float* W2  = (const float*)d_in[10];
    const float* as2 = (const float*)d_in[11];
    const float* ad2 = (const float*)d_in[12];
    const float* b2  = (const float*)d_in[13];
    float* out = (float*)d_out;

    int N = in_sizes[0] / 128;
    int E = in_sizes[1] / 2;
    int ET = E + N;

    float *feat, *inb, *asb, *adb;
    int *srcp, *dstp, *csrc, *cnt, *fill, *rowptr, *bsum;
    cudaGetSymbolAddress((void**)&feat,   g_feat);
    cudaGetSymbolAddress((void**)&inb,    g_in);
    cudaGetSymbolAddress((void**)&asb,    g_as);
    cudaGetSymbolAddress((void**)&adb,    g_ad);
    cudaGetSymbolAddress((void**)&srcp,   g_src);
    cudaGetSymbolAddress((void**)&dstp,   g_dst);
    cudaGetSymbolAddress((void**)&csrc,   g_csrc);
    cudaGetSymbolAddress((void**)&cnt,    g_cnt);
    cudaGetSymbolAddress((void**)&fill,   g_fill);
    cudaGetSymbolAddress((void**)&rowptr, g_rowptr);
    cudaGetSymbolAddress((void**)&bsum,   g_bsum);

    const int TB = 256;
    int gemmGrid = (N + 127) / 128;
    int aggGrid = ((long)N * 32 + TB - 1) / TB;
    int nchunk = (N + 1023) / 1024;

    const int SM128 = (128 * 68 + 64 * 132) * 4;   // 68608 B
    const int SM64  = (128 * 68 + 64 * 68) * 4;    // 52224 B
    cudaFuncSetAttribute(gemm_tc<128, 4>, cudaFuncAttributeMaxDynamicSharedMemorySize, SM128);
    cudaFuncSetAttribute(gemm_tc<64, 1>,  cudaFuncAttributeMaxDynamicSharedMemorySize, SM64);

    static cudaStream_t s2 = nullptr;
    static cudaEvent_t evFork = nullptr, evJoin = nullptr;
    if (s2 == nullptr) {
        cudaStreamCreateWithFlags(&s2, cudaStreamNonBlocking);
        cudaEventCreateWithFlags(&evFork, cudaEventDisableTiming);
        cudaEventCreateWithFlags(&evJoin, cudaEventDisableTiming);
    }

    // ---- fork: CSR build on s2, concurrent with layer-0 GEMM ----
    cudaEventRecord(evFork, 0);
    cudaStreamWaitEvent(s2, evFork, 0);

    detect_k<<<1, 1, 0, s2>>>((const unsigned int*)ei);
    zero_k<<<(N + TB - 1) / TB, TB, 0, s2>>>(cnt, fill, N);
    decode_hist_k<<<(ET + TB - 1) / TB, TB, 0, s2>>>(ei, E, ET, srcp, dstp, cnt);
    scan1_k<<<nchunk, 1024, 0, s2>>>(cnt, rowptr, bsum, N);
    scan2_k<<<1, 64, 0, s2>>>(bsum, nchunk, rowptr, N);
    scan3_k<<<(N + TB - 1) / TB, TB, 0, s2>>>(rowptr, bsum, N);
    scatter_k<<<(ET + TB - 1) / TB, TB, 0, s2>>>(srcp, dstp, ET, rowptr, fill, csrc);
    cudaEventRecord(evJoin, s2);

    // ---------------- Layer 0 (GEMM overlaps CSR build) ----------------
    gemm_tc<128, 4><<<gemmGrid, TB, SM128>>>(x, W0, feat, as0, ad0, asb, adb, N);
    cudaStreamWaitEvent(0, evJoin, 0);
    agg128_k<<<aggGrid, TB>>>(rowptr, csrc, feat, asb, adb, b0, inb, N);

    // ---------------- Layer 1 ----------------
    gemm_tc<128, 4><<<gemmGrid, TB, SM128>>>(inb, W1, feat, as1, ad1, asb, adb, N);
    agg128_k<<<aggGrid, TB>>>(rowptr, csrc, feat, asb, adb, b1, inb, N);

    // ---------------- Layer 2 ----------------
    gemm_tc<64, 1><<<gemmGrid, TB, SM64>>>(inb, W2, feat, as2, ad2, asb, adb, N);
    agg64_k<<<aggGrid, TB>>>(rowptr, csrc, feat, asb, adb, b2, out, N);
}

// round 16
// speedup vs baseline: 1.1380x; 1.1201x over previous
#include <cuda_runtime.h>
#include <cstdint>

// ---------------------------------------------------------------------------
// GAT encoder, 3 layers. Round 16: GEMM 2-term tf32 split — A = hi+lo (exact
// to fp32), B truncated to tf32. D = Ahi*Bhi + Alo*Bhi. Injects ~2.4e-4 RMS
// noise on W products; round-14 fp16 experiment measured ~10x attenuation to
// final output -> expect ~1e-4 rel_err. Mainloop: 96 issue slots/kc vs 144.
// Agg = round-13 simple single-sweep. CSR on forked stream. Base: 206.2us.
// ---------------------------------------------------------------------------

#define MAXN 50000
#define MAXE 800000
#define MAXET (MAXE + MAXN)

__device__ __align__(16) float g_feat[MAXN * 128];
__device__ __align__(16) float g_in  [MAXN * 128];
__device__ __align__(16) float g_as  [MAXN * 4];
__device__ __align__(16) float g_ad  [MAXN * 4];
__device__ int g_src [MAXET];
__device__ int g_dst [MAXET];
__device__ int g_csrc[MAXET];
__device__ int g_cnt [MAXN];
__device__ int g_fill[MAXN];
__device__ int g_rowptr[MAXN + 1];
__device__ int g_bsum[64];
__device__ int g_is64;

// ---------------------------------------------------------------------------
__global__ void detect_k(const unsigned int* __restrict__ raw) {
    unsigned int o = 0;
#pragma unroll
    for (int j = 1; j < 128; j += 2) o |= raw[j];
    g_is64 = (o == 0u) ? 1 : 0;
}

__global__ void zero_k(int* __restrict__ cnt, int* __restrict__ fill, int N) {
    int i = blockIdx.x * blockDim.x + threadIdx.x;
    if (i < N) { cnt[i] = 0; fill[i] = 0; }
}

__global__ void decode_hist_k(const void* __restrict__ raw, int E, int ET,
                              int* __restrict__ src, int* __restrict__ dst,
                              int* __restrict__ cnt) {
    int e = blockIdx.x * blockDim.x + threadIdx.x;
    if (e >= ET) return;
    int s, d;
    if (e < E) {
        if (g_is64) {
            const long long* p = (const long long*)raw;
            s = (int)p[e];
            d = (int)p[E + e];
        } else {
            const int* p = (const int*)raw;
            s = p[e];
            d = p[E + e];
        }
    } else {
        s = d = e - E;
    }
    src[e] = s;
    dst[e] = d;
    atomicAdd(&cnt[d], 1);
}

__device__ __forceinline__ int warp_incl_scan(int v) {
    int lane = threadIdx.x & 31;
#pragma unroll
    for (int o = 1; o < 32; o <<= 1) {
        int t = __shfl_up_sync(0xffffffffu, v, o);
        if (lane >= o) v += t;
    }
    return v;
}

__global__ __launch_bounds__(1024) void scan1_k(const int* __restrict__ cnt,
                                                int* __restrict__ rowptr,
                                                int* __restrict__ bsum, int N) {
    __shared__ int wsum[32];
    int tid = threadIdx.x;
    int idx = blockIdx.x * 1024 + tid;
    int wid = tid >> 5, lane = tid & 31;
    int v = (idx < N) ? cnt[idx] : 0;
    int inc = warp_incl_scan(v);
    if (lane == 31) wsum[wid] = inc;
    __syncthreads();
    if (wid == 0) {
        int w = wsum[lane];
        wsum[lane] = warp_incl_scan(w);
    }
    __syncthreads();
    int off = (wid > 0) ? wsum[wid - 1] : 0;
    if (idx < N) rowptr[idx] = off + inc - v;
    if (tid == 1023) bsum[blockIdx.x] = off + inc;
}

__global__ void scan2_k(int* __restrict__ bsum, int nb, int* __restrict__ rowptr, int N) {
    __shared__ int sh[64];
    int tid = threadIdx.x;
    sh[tid] = (tid < nb) ? bsum[tid] : 0;
    __syncthreads();
    for (int o = 1; o < 64; o <<= 1) {
        int t = (tid >= o) ? sh[tid - o] : 0;
        __syncthreads();
        sh[tid] += t;
        __syncthreads();
    }
    if (tid < nb) bsum[tid] = (tid > 0) ? sh[tid - 1] : 0;
    if (tid == 0) rowptr[N] = sh[nb - 1];
}

__global__ void scan3_k(int* __restrict__ rowptr, const int* __restrict__ bsum, int N) {
    int idx = blockIdx.x * blockDim.x + threadIdx.x;
    if (idx < N) rowptr[idx] += bsum[idx >> 10];
}

__global__ void scatter_k(const int* __restrict__ src, const int* __restrict__ dst,
                          int ET, const int* __restrict__ rowptr,
                          int* __restrict__ fill, int* __restrict__ csrc) {
    int e = blockIdx.x * blockDim.x + threadIdx.x;
    if (e >= ET) return;
    int d = dst[e];
    int pos = rowptr[d] + atomicAdd(&fill[d], 1);
    csrc[pos] = src[e];
}

// ---------------------------------------------------------------------------
// tf32 helpers
// ---------------------------------------------------------------------------
__device__ __forceinline__ uint32_t f2tf(float f) {
    uint32_t u;
    asm("cvt.rna.tf32.f32 %0, %1;" : "=r"(u) : "f"(f));
    return u;
}

__device__ __forceinline__ void mma8(float4& d, const uint32_t* a, const uint32_t* b) {
    asm volatile(
        "mma.sync.aligned.m16n8k8.row.col.f32.tf32.tf32.f32 "
        "{%0,%1,%2,%3}, {%4,%5,%6,%7}, {%8,%9}, {%0,%1,%2,%3};"
        : "+f"(d.x), "+f"(d.y), "+f"(d.z), "+f"(d.w)
        : "r"(a[0]), "r"(a[1]), "r"(a[2]), "r"(a[3]), "r"(b[0]), "r"(b[1]));
}

// ---------------------------------------------------------------------------
// Tensor-core GEMM: 2-term split. A exact (hi+lo), B tf32-truncated.
// D = Ahi*Bhi + Alo*Bhi. KC=64, same tiling as round 10.
// ---------------------------------------------------------------------------
template <int NC, int HH>
__global__ __launch_bounds__(256) void gemm_tc(const float* __restrict__ X,
                                               const float* __restrict__ W,
                                               float* __restrict__ O,
                                               const float* __restrict__ avs,
                                               const float* __restrict__ avd,
                                               float* __restrict__ os,
                                               float* __restrict__ od, int M) {
    constexpr int KC = 64;
    constexpr int XSS = 68;
    constexpr int WSS = NC + 4;
    constexpr int CGW = NC / 2;
    constexpr int NT  = CGW / 8;
    constexpr int LH  = (HH == 4) ? 2 : 1;

    extern __shared__ float smem[];
    float* Xs = smem;
    float* Ws = smem + 128 * XSS;

    int tid = threadIdx.x;
    int warp = tid >> 5, lane = tid & 31;
    int rg = warp >> 1, cg2 = warp & 1;
    int lr = lane >> 2, lc = lane & 3;
    int rowbase = blockIdx.x * 128;

    float4 acc[2][NT];
#pragma unroll
    for (int mt = 0; mt < 2; mt++)
#pragma unroll
        for (int nt = 0; nt < NT; nt++)
            acc[mt][nt] = make_float4(0.f, 0.f, 0.f, 0.f);

    for (int kb = 0; kb < 128; kb += KC) {
        __syncthreads();
#pragma unroll
        for (int i = 0; i < 8; i++) {
            int t = tid + i * 256;
            int row = t >> 4, q = t & 15;
            float4 v = make_float4(0.f, 0.f, 0.f, 0.f);
            if (rowbase + row < M)
                v = *reinterpret_cast<const float4*>(X + (size_t)(rowbase + row) * 128 + kb + q * 4);
            reinterpret_cast<float4*>(Xs + row * XSS)[q] = v;
        }
#pragma unroll
        for (int i = 0; i < (KC * NC / 4) / 256; i++) {
            int t = tid + i * 256;
            int k = t / (NC / 4), q = t % (NC / 4);
            float4 v = *reinterpret_cast<const float4*>(W + (size_t)(kb + k) * NC + q * 4);
            reinterpret_cast<float4*>(Ws + k * WSS)[q] = v;
        }
        __syncthreads();

#pragma unroll
        for (int kc = 0; kc < KC / 8; kc++) {
            uint32_t ah[2][4], al[2][4];
#pragma unroll
            for (int mt = 0; mt < 2; mt++) {
                const float* ab = Xs + (rg * 32 + mt * 16 + lr) * XSS + kc * 8 + lc;
                float f0 = ab[0];
                float f1 = ab[8 * XSS];
                float f2 = ab[4];
                float f3 = ab[8 * XSS + 4];
                ah[mt][0] = f2tf(f0); al[mt][0] = f2tf(f0 - __uint_as_float(ah[mt][0]));
                ah[mt][1] = f2tf(f1); al[mt][1] = f2tf(f1 - __uint_as_float(ah[mt][1]));
                ah[mt][2] = f2tf(f2); al[mt][2] = f2tf(f2 - __uint_as_float(ah[mt][2]));
                ah[mt][3] = f2tf(f3); al[mt][3] = f2tf(f3 - __uint_as_float(ah[mt][3]));
            }
#pragma unroll
            for (int nt = 0; nt < NT; nt++) {
                const float* bb = Ws + (kc * 8 + lc) * WSS + cg2 * CGW + nt * 8 + lr;
                uint32_t bh[2];
                bh[0] = f2tf(bb[0]);
                bh[1] = f2tf(bb[4 * WSS]);
#pragma unroll
                for (int mt = 0; mt < 2; mt++) {
                    mma8(acc[mt][nt], ah[mt], bh);
                    mma8(acc[mt][nt], al[mt], bh);
                }
            }
        }
    }

    float sA[2][2][LH], sD[2][2][LH];
#pragma unroll
    for (int mt = 0; mt < 2; mt++)
#pragma unroll
        for (int rs = 0; rs < 2; rs++)
#pragma unroll
            for (int lh = 0; lh < LH; lh++) { sA[mt][rs][lh] = 0.f; sD[mt][rs][lh] = 0.f; }

#pragma unroll
    for (int mt = 0; mt < 2; mt++) {
        int r0 = rowbase + rg * 32 + mt * 16 + lr;
#pragma unroll
        for (int nt = 0; nt < NT; nt++) {
            int col = cg2 * CGW + nt * 8 + 2 * lc;
            float4 d = acc[mt][nt];
            float av0 = __ldg(avs + col), av1 = __ldg(avs + col + 1);
            float dv0 = __ldg(avd + col), dv1 = __ldg(avd + col + 1);
            int lh = (HH == 4) ? (nt / (NT / 2)) : 0;
            sA[mt][0][lh] += d.x * av0 + d.y * av1;
            sD[mt][0][lh] += d.x * dv0 + d.y * dv1;
            sA[mt][1][lh] += d.z * av0 + d.w * av1;
            sD[mt][1][lh] += d.z * dv0 + d.w * dv1;
            if (r0 < M)
                *reinterpret_cast<float2*>(O + (size_t)r0 * NC + col) = make_float2(d.x, d.y);
            if (r0 + 8 < M)
                *reinterpret_cast<float2*>(O + (size_t)(r0 + 8) * NC + col) = make_float2(d.z, d.w);
        }
    }

#pragma unroll
    for (int mt = 0; mt < 2; mt++)
#pragma unroll
        for (int rs = 0; rs < 2; rs++)
#pragma unroll
            for (int lh = 0; lh < LH; lh++) {
                float a = sA[mt][rs][lh], d = sD[mt][rs][lh];
                a += __shfl_xor_sync(0xffffffffu, a, 1);
                a += __shfl_xor_sync(0xffffffffu, a, 2);
                d += __shfl_xor_sync(0xffffffffu, d, 1);
                d += __shfl_xor_sync(0xffffffffu, d, 2);
                sA[mt][rs][lh] = a; sD[mt][rs][lh] = d;
            }

    if (HH == 4) {
        if (lc == 0) {
#pragma unroll
            for (int mt = 0; mt < 2; mt++)
#pragma unroll
                for (int rs = 0; rs < 2; rs++) {
                    int row = rowbase + rg * 32 + mt * 16 + rs * 8 + lr;
                    if (row < M) {
#pragma unroll
                        for (int lh = 0; lh < LH; lh++) {
                            os[row * 4 + cg2 * 2 + lh] = sA[mt][rs][lh];
                            od[row * 4 + cg2 * 2 + lh] = sD[mt][rs][lh];
                        }
                    }
                }
        }
    } else {
        __syncthreads();
        float* sp = smem;
        float* dp = smem + 256;
        if (lc == 0) {
#pragma unroll
            for (int mt = 0; mt < 2; mt++)
#pragma unroll
                for (int rs = 0; rs < 2; rs++) {
                    int lrow = rg * 32 + mt * 16 + rs * 8 + lr;
                    sp[lrow * 2 + cg2] = sA[mt][rs][0];
                    dp[lrow * 2 + cg2] = sD[mt][rs][0];
                }
        }
        __syncthreads();
        if (tid < 128) {
            int row = rowbase + tid;
            if (row < M) {
                os[row] = sp[tid * 2] + sp[tid * 2 + 1];
                od[row] = dp[tid * 2] + dp[tid * 2 + 1];
            }
        }
    }
}

// ---------------------------------------------------------------------------
// CSR aggregation, single sweep (round-13 version).
// ---------------------------------------------------------------------------
__global__ __launch_bounds__(256) void agg128_k(const int* __restrict__ rowptr,
                                                const int* __restrict__ csrc,
                                                const float* __restrict__ feat,
                                                const float* __restrict__ as_,
                                                const float* __restrict__ ad_,
                                                const float* __restrict__ b,
                                                float* __restrict__ out, int N) {
    int gt = blockIdx.x * blockDim.x + threadIdx.x;
    int n = gt >> 5;
    int lane = gt & 31;
    if (n >= N) return;
    int h = lane >> 3;
    float adv = __ldg(ad_ + n * 4 + h);
    int p0 = __ldg(rowptr + n), p1 = __ldg(rowptr + n + 1);

    float den = 0.f;
    float4 acc = make_float4(0.f, 0.f, 0.f, 0.f);
    for (int i = p0; i < p1; i++) {
        int s = __ldg(csrc + i);
        float4 f = __ldg(reinterpret_cast<const float4*>(feat) + (size_t)s * 32 + lane);
        float v = __ldg(as_ + s * 4 + h) + adv;
        v = v > 0.f ? v : 0.2f * v;
        float ex = __expf(v);
        den += ex;
        acc.x += ex * f.x; acc.y += ex * f.y;
        acc.z += ex * f.z; acc.w += ex * f.w;
    }

    float w = 1.f / (den + 1e-16f);
    float4 bb = *reinterpret_cast<const float4*>(b + lane * 4);
    float4 o;
    o.x = fmaxf(acc.x * w + bb.x, 0.f);
    o.y = fmaxf(acc.y * w + bb.y, 0.f);
    o.z = fmaxf(acc.z * w + bb.z, 0.f);
    o.w = fmaxf(acc.w * w + bb.w, 0.f);
    reinterpret_cast<float4*>(out)[(size_t)n * 32 + lane] = o;
}

__global__ __launch_bounds__(256) void agg64_k(const int* __restrict__ rowptr,
                                               const int* __restrict__ csrc,
                                               const float* __restrict__ feat,
                                               const float* __restrict__ as_,
                                               const float* __restrict__ ad_,
                                               const float* __restrict__ b,
                                               float* __restrict__ out, int N) {
    int gt = blockIdx.x * blockDim.x + threadIdx.x;
    int n = gt >> 5;
    int lane = gt & 31;
    if (n >= N) return;
    float adv = __ldg(ad_ + n);
    int p0 = __ldg(rowptr + n), p1 = __ldg(rowptr + n + 1);

    float den = 0.f;
    float2 acc = make_float2(0.f, 0.f);
    for (int i = p0; i < p1; i++) {
        int s = __ldg(csrc + i);
        float2 f = __ldg(reinterpret_cast<const float2*>(feat) + (size_t)s * 32 + lane);
        float v = __ldg(as_ + s) + adv;
        v = v > 0.f ? v : 0.2f * v;
        float ex = __expf(v);
        den += ex;
        acc.x += ex * f.x; acc.y += ex * f.y;
    }

    float w = 1.f / (den + 1e-16f);
    float2 bb = *reinterpret_cast<const float2*>(b + lane * 2);
    float2 o;
    o.x = acc.x * w + bb.x;
    o.y = acc.y * w + bb.y;
    reinterpret_cast<float2*>(out)[(size_t)n * 32 + lane] = o;
}

// ---------------------------------------------------------------------------
extern "C" void kernel_launch(void* const* d_in, const int* in_sizes, int n_in,
                              void* d_out, int out_size) {
    const float* x   = (const float*)d_in[0];
    const void*  ei  = d_in[1];
    const float* W0  = (const float*)d_in[2];
    const float* as0 = (const float*)d_in[3];
    const float* ad0 = (const float*)d_in[4];
    const float* b0  = (const float*)d_in[5];
    const float* W1  = (const float*)d_in[6];
    const float* as1 = (const float*)d_in[7];
    const float* ad1 = (const float*)d_in[8];
    const float* b1  = (const float*)d_in[9];
    const float* W2  = (const float*)d_in[10];
    const float* as2 = (const float*)d_in[11];
    const float* ad2 = (const float*)d_in[12];
    const float* b2  = (const float*)d_in[13];
    float* out = (float*)d_out;

    int N = in_sizes[0] / 128;
    int E = in_sizes[1] / 2;
    int ET = E + N;

    float *feat, *inb, *asb, *adb;
    int *srcp, *dstp, *csrc, *cnt, *fill, *rowptr, *bsum;
    cudaGetSymbolAddress((void**)&feat,   g_feat);
    cudaGetSymbolAddress((void**)&inb,    g_in);
    cudaGetSymbolAddress((void**)&asb,    g_as);
    cudaGetSymbolAddress((void**)&adb,    g_ad);
    cudaGetSymbolAddress((void**)&srcp,   g_src);
    cudaGetSymbolAddress((void**)&dstp,   g_dst);
    cudaGetSymbolAddress((void**)&csrc,   g_csrc);
    cudaGetSymbolAddress((void**)&cnt,    g_cnt);
    cudaGetSymbolAddress((void**)&fill,   g_fill);
    cudaGetSymbolAddress((void**)&rowptr, g_rowptr);
    cudaGetSymbolAddress((void**)&bsum,   g_bsum);

    const int TB = 256;
    int gemmGrid = (N + 127) / 128;
    int aggGrid = ((long)N * 32 + TB - 1) / TB;
    int nchunk = (N + 1023) / 1024;

    const int SM128 = (128 * 68 + 64 * 132) * 4;   // 68608 B
    const int SM64  = (128 * 68 + 64 * 68) * 4;    // 52224 B
    cudaFuncSetAttribute(gemm_tc<128, 4>, cudaFuncAttributeMaxDynamicSharedMemorySize, SM128);
    cudaFuncSetAttribute(gemm_tc<64, 1>,  cudaFuncAttributeMaxDynamicSharedMemorySize, SM64);

    static cudaStream_t s2 = nullptr;
    static cudaEvent_t evFork = nullptr, evJoin = nullptr;
    if (s2 == nullptr) {
        cudaStreamCreateWithFlags(&s2, cudaStreamNonBlocking);
        cudaEventCreateWithFlags(&evFork, cudaEventDisableTiming);
        cudaEventCreateWithFlags(&evJoin, cudaEventDisableTiming);
    }

    // ---- fork: CSR build on s2, concurrent with layer-0 GEMM ----
    cudaEventRecord(evFork, 0);
    cudaStreamWaitEvent(s2, evFork, 0);

    detect_k<<<1, 1, 0, s2>>>((const unsigned int*)ei);
    zero_k<<<(N + TB - 1) / TB, TB, 0, s2>>>(cnt, fill, N);
    decode_hist_k<<<(ET + TB - 1) / TB, TB, 0, s2>>>(ei, E, ET, srcp, dstp, cnt);
    scan1_k<<<nchunk, 1024, 0, s2>>>(cnt, rowptr, bsum, N);
    scan2_k<<<1, 64, 0, s2>>>(bsum, nchunk, rowptr, N);
    scan3_k<<<(N + TB - 1) / TB, TB, 0, s2>>>(rowptr, bsum, N);
    scatter_k<<<(ET + TB - 1) / TB, TB, 0, s2>>>(srcp, dstp, ET, rowptr, fill, csrc);
    cudaEventRecord(evJoin, s2);

    // ---------------- Layer 0 (GEMM overlaps CSR build) ----------------
    gemm_tc<128, 4><<<gemmGrid, TB, SM128>>>(x, W0, feat, as0, ad0, asb, adb, N);
    cudaStreamWaitEvent(0, evJoin, 0);
    agg128_k<<<aggGrid, TB>>>(rowptr, csrc, feat, asb, adb, b0, inb, N);

    // ---------------- Layer 1 ----------------
    gemm_tc<128, 4><<<gemmGrid, TB, SM128>>>(inb, W1, feat, as1, ad1, asb, adb, N);
    agg128_k<<<aggGrid, TB>>>(rowptr, csrc, feat, asb, adb, b1, inb, N);

    // ---------------- Layer 2 ----------------
    gemm_tc<64, 1><<<gemmGrid, TB, SM64>>>(inb, W2, feat, as2, ad2, asb, adb, N);
    agg64_k<<<aggGrid, TB>>>(rowptr, csrc, feat, asb, adb, b2, out, N);
}

// round 17
// speedup vs baseline: 1.1576x; 1.0173x over previous
#include <cuda_runtime.h>
#include <cstdint>

// ---------------------------------------------------------------------------
// GAT encoder, 3 layers. Round 17: precision reallocated by attenuation.
//  - Layers 0/1 GEMM: 1-term pure tf32, converted AT STAGING (in-place bits,
//    no extra smem) -> mainloop is pure LDS+MMA. Error ~4e-4 attenuated ~10x.
//  - Layer 2 GEMM: 3-term split (unattenuated path, must be accurate).
// Agg single-sweep, CSR on forked stream (round 13). Base: 184.6us.
// ---------------------------------------------------------------------------

#define MAXN 50000
#define MAXE 800000
#define MAXET (MAXE + MAXN)

__device__ __align__(16) float g_feat[MAXN * 128];
__device__ __align__(16) float g_in  [MAXN * 128];
__device__ __align__(16) float g_as  [MAXN * 4];
__device__ __align__(16) float g_ad  [MAXN * 4];
__device__ int g_src [MAXET];
__device__ int g_dst [MAXET];
__device__ int g_csrc[MAXET];
__device__ int g_cnt [MAXN];
__device__ int g_fill[MAXN];
__device__ int g_rowptr[MAXN + 1];
__device__ int g_bsum[64];
__device__ int g_is64;

// ---------------------------------------------------------------------------
__global__ void detect_k(const unsigned int* __restrict__ raw) {
    unsigned int o = 0;
#pragma unroll
    for (int j = 1; j < 128; j += 2) o |= raw[j];
    g_is64 = (o == 0u) ? 1 : 0;
}

__global__ void zero_k(int* __restrict__ cnt, int* __restrict__ fill, int N) {
    int i = blockIdx.x * blockDim.x + threadIdx.x;
    if (i < N) { cnt[i] = 0; fill[i] = 0; }
}

__global__ void decode_hist_k(const void* __restrict__ raw, int E, int ET,
                              int* __restrict__ src, int* __restrict__ dst,
                              int* __restrict__ cnt) {
    int e = blockIdx.x * blockDim.x + threadIdx.x;
    if (e >= ET) return;
    int s, d;
    if (e < E) {
        if (g_is64) {
            const long long* p = (const long long*)raw;
            s = (int)p[e];
            d = (int)p[E + e];
        } else {
            const int* p = (const int*)raw;
            s = p[e];
            d = p[E + e];
        }
    } else {
        s = d = e - E;
    }
    src[e] = s;
    dst[e] = d;
    atomicAdd(&cnt[d], 1);
}

__device__ __forceinline__ int warp_incl_scan(int v) {
    int lane = threadIdx.x & 31;
#pragma unroll
    for (int o = 1; o < 32; o <<= 1) {
        int t = __shfl_up_sync(0xffffffffu, v, o);
        if (lane >= o) v += t;
    }
    return v;
}

__global__ __launch_bounds__(1024) void scan1_k(const int* __restrict__ cnt,
                                                int* __restrict__ rowptr,
                                                int* __restrict__ bsum, int N) {
    __shared__ int wsum[32];
    int tid = threadIdx.x;
    int idx = blockIdx.x * 1024 + tid;
    int wid = tid >> 5, lane = tid & 31;
    int v = (idx < N) ? cnt[idx] : 0;
    int inc = warp_incl_scan(v);
    if (lane == 31) wsum[wid] = inc;
    __syncthreads();
    if (wid == 0) {
        int w = wsum[lane];
        wsum[lane] = warp_incl_scan(w);
    }
    __syncthreads();
    int off = (wid > 0) ? wsum[wid - 1] : 0;
    if (idx < N) rowptr[idx] = off + inc - v;
    if (tid == 1023) bsum[blockIdx.x] = off + inc;
}

__global__ void scan2_k(int* __restrict__ bsum, int nb, int* __restrict__ rowptr, int N) {
    __shared__ int sh[64];
    int tid = threadIdx.x;
    sh[tid] = (tid < nb) ? bsum[tid] : 0;
    __syncthreads();
    for (int o = 1; o < 64; o <<= 1) {
        int t = (tid >= o) ? sh[tid - o] : 0;
        __syncthreads();
        sh[tid] += t;
        __syncthreads();
    }
    if (tid < nb) bsum[tid] = (tid > 0) ? sh[tid - 1] : 0;
    if (tid == 0) rowptr[N] = sh[nb - 1];
}

__global__ void scan3_k(int* __restrict__ rowptr, const int* __restrict__ bsum, int N) {
    int idx = blockIdx.x * blockDim.x + threadIdx.x;
    if (idx < N) rowptr[idx] += bsum[idx >> 10];
}

__global__ void scatter_k(const int* __restrict__ src, const int* __restrict__ dst,
                          int ET, const int* __restrict__ rowptr,
                          int* __restrict__ fill, int* __restrict__ csrc) {
    int e = blockIdx.x * blockDim.x + threadIdx.x;
    if (e >= ET) return;
    int d = dst[e];
    int pos = rowptr[d] + atomicAdd(&fill[d], 1);
    csrc[pos] = src[e];
}

// ---------------------------------------------------------------------------
// tf32 helpers
// ---------------------------------------------------------------------------
__device__ __forceinline__ uint32_t f2tf(float f) {
    uint32_t u;
    asm("cvt.rna.tf32.f32 %0, %1;" : "=r"(u) : "f"(f));
    return u;
}

__device__ __forceinline__ void mma8(float4& d, const uint32_t* a, const uint32_t* b) {
    asm volatile(
        "mma.sync.aligned.m16n8k8.row.col.f32.tf32.tf32.f32 "
        "{%0,%1,%2,%3}, {%4,%5,%6,%7}, {%8,%9}, {%0,%1,%2,%3};"
        : "+f"(d.x), "+f"(d.y), "+f"(d.z), "+f"(d.w)
        : "r"(a[0]), "r"(a[1]), "r"(a[2]), "r"(a[3]), "r"(b[0]), "r"(b[1]));
}

// ---------------------------------------------------------------------------
// Tensor-core GEMM.
// TERMS==1: pure tf32, converted at staging (in-place), mainloop LDS+MMA only.
// TERMS==3: fp32-grade 3-term split with in-loop cvt (round-10 path).
// ---------------------------------------------------------------------------
template <int NC, int HH, int TERMS>
__global__ __launch_bounds__(256) void gemm_tc(const float* __restrict__ X,
                                               const float* __restrict__ W,
                                               float* __restrict__ O,
                                               const float* __restrict__ avs,
                                               const float* __restrict__ avd,
                                               float* __restrict__ os,
                                               float* __restrict__ od, int M) {
    constexpr int KC = 64;
    constexpr int XSS = 68;
    constexpr int WSS = NC + 4;
    constexpr int CGW = NC / 2;
    constexpr int NT  = CGW / 8;
    constexpr int LH  = (HH == 4) ? 2 : 1;

    extern __shared__ float smem[];
    float* Xs = smem;
    float* Ws = smem + 128 * XSS;
    uint32_t* Xu = reinterpret_cast<uint32_t*>(Xs);
    uint32_t* Wu = reinterpret_cast<uint32_t*>(Ws);

    int tid = threadIdx.x;
    int warp = tid >> 5, lane = tid & 31;
    int rg = warp >> 1, cg2 = warp & 1;
    int lr = lane >> 2, lc = lane & 3;
    int rowbase = blockIdx.x * 128;

    float4 acc[2][NT];
#pragma unroll
    for (int mt = 0; mt < 2; mt++)
#pragma unroll
        for (int nt = 0; nt < NT; nt++)
            acc[mt][nt] = make_float4(0.f, 0.f, 0.f, 0.f);

    for (int kb = 0; kb < 128; kb += KC) {
        __syncthreads();
#pragma unroll
        for (int i = 0; i < 8; i++) {
            int t = tid + i * 256;
            int row = t >> 4, q = t & 15;
            float4 v = make_float4(0.f, 0.f, 0.f, 0.f);
            if (rowbase + row < M)
                v = *reinterpret_cast<const float4*>(X + (size_t)(rowbase + row) * 128 + kb + q * 4);
            if (TERMS == 1) {
                uint4 u;
                u.x = f2tf(v.x); u.y = f2tf(v.y); u.z = f2tf(v.z); u.w = f2tf(v.w);
                reinterpret_cast<uint4*>(Xu + row * XSS)[q] = u;
            } else {
                reinterpret_cast<float4*>(Xs + row * XSS)[q] = v;
            }
        }
#pragma unroll
        for (int i = 0; i < (KC * NC / 4) / 256; i++) {
            int t = tid + i * 256;
            int k = t / (NC / 4), q = t % (NC / 4);
            float4 v = *reinterpret_cast<const float4*>(W + (size_t)(kb + k) * NC + q * 4);
            if (TERMS == 1) {
                uint4 u;
                u.x = f2tf(v.x); u.y = f2tf(v.y); u.z = f2tf(v.z); u.w = f2tf(v.w);
                reinterpret_cast<uint4*>(Wu + k * WSS)[q] = u;
            } else {
                reinterpret_cast<float4*>(Ws + k * WSS)[q] = v;
            }
        }
        __syncthreads();

#pragma unroll
        for (int kc = 0; kc < KC / 8; kc++) {
            if (TERMS == 1) {
                uint32_t ah[2][4];
#pragma unroll
                for (int mt = 0; mt < 2; mt++) {
                    const uint32_t* ab = Xu + (rg * 32 + mt * 16 + lr) * XSS + kc * 8 + lc;
                    ah[mt][0] = ab[0];
                    ah[mt][1] = ab[8 * XSS];
                    ah[mt][2] = ab[4];
                    ah[mt][3] = ab[8 * XSS + 4];
                }
#pragma unroll
                for (int nt = 0; nt < NT; nt++) {
                    const uint32_t* bb = Wu + (kc * 8 + lc) * WSS + cg2 * CGW + nt * 8 + lr;
                    uint32_t bh[2] = {bb[0], bb[4 * WSS]};
#pragma unroll
                    for (int mt = 0; mt < 2; mt++)
                        mma8(acc[mt][nt], ah[mt], bh);
                }
            } else {
                uint32_t ah[2][4], al[2][4];
#pragma unroll
                for (int mt = 0; mt < 2; mt++) {
                    const float* ab = Xs + (rg * 32 + mt * 16 + lr) * XSS + kc * 8 + lc;
                    float f0 = ab[0];
                    float f1 = ab[8 * XSS];
                    float f2 = ab[4];
                    float f3 = ab[8 * XSS + 4];
                    ah[mt][0] = f2tf(f0); al[mt][0] = f2tf(f0 - __uint_as_float(ah[mt][0]));
                    ah[mt][1] = f2tf(f1); al[mt][1] = f2tf(f1 - __uint_as_float(ah[mt][1]));
                    ah[mt][2] = f2tf(f2); al[mt][2] = f2tf(f2 - __uint_as_float(ah[mt][2]));
                    ah[mt][3] = f2tf(f3); al[mt][3] = f2tf(f3 - __uint_as_float(ah[mt][3]));
                }
#pragma unroll
                for (int nt = 0; nt < NT; nt++) {
                    const float* bb = Ws + (kc * 8 + lc) * WSS + cg2 * CGW + nt * 8 + lr;
                    float g0 = bb[0];
                    float g1 = bb[4 * WSS];
                    uint32_t bh[2], bl[2];
                    bh[0] = f2tf(g0); bl[0] = f2tf(g0 - __uint_as_float(bh[0]));
                    bh[1] = f2tf(g1); bl[1] = f2tf(g1 - __uint_as_float(bh[1]));
#pragma unroll
                    for (int mt = 0; mt < 2; mt++) {
                        mma8(acc[mt][nt], ah[mt], bh);
                        mma8(acc[mt][nt], ah[mt], bl);
                        mma8(acc[mt][nt], al[mt], bh);
                    }
                }
            }
        }
    }

    float sA[2][2][LH], sD[2][2][LH];
#pragma unroll
    for (int mt = 0; mt < 2; mt++)
#pragma unroll
        for (int rs = 0; rs < 2; rs++)
#pragma unroll
            for (int lh = 0; lh < LH; lh++) { sA[mt][rs][lh] = 0.f; sD[mt][rs][lh] = 0.f; }

#pragma unroll
    for (int mt = 0; mt < 2; mt++) {
        int r0 = rowbase + rg * 32 + mt * 16 + lr;
#pragma unroll
        for (int nt = 0; nt < NT; nt++) {
            int col = cg2 * CGW + nt * 8 + 2 * lc;
            float4 d = acc[mt][nt];
            float av0 = __ldg(avs + col), av1 = __ldg(avs + col + 1);
            float dv0 = __ldg(avd + col), dv1 = __ldg(avd + col + 1);
            int lh = (HH == 4) ? (nt / (NT / 2)) : 0;
            sA[mt][0][lh] += d.x * av0 + d.y * av1;
            sD[mt][0][lh] += d.x * dv0 + d.y * dv1;
            sA[mt][1][lh] += d.z * av0 + d.w * av1;
            sD[mt][1][lh] += d.z * dv0 + d.w * dv1;
            if (r0 < M)
                *reinterpret_cast<float2*>(O + (size_t)r0 * NC + col) = make_float2(d.x, d.y);
            if (r0 + 8 < M)
                *reinterpret_cast<float2*>(O + (size_t)(r0 + 8) * NC + col) = make_float2(d.z, d.w);
        }
    }

#pragma unroll
    for (int mt = 0; mt < 2; mt++)
#pragma unroll
        for (int rs = 0; rs < 2; rs++)
#pragma unroll
            for (int lh = 0; lh < LH; lh++) {
                float a = sA[mt][rs][lh], d = sD[mt][rs][lh];
                a += __shfl_xor_sync(0xffffffffu, a, 1);
                a += __shfl_xor_sync(0xffffffffu, a, 2);
                d += __shfl_xor_sync(0xffffffffu, d, 1);
                d += __shfl_xor_sync(0xffffffffu, d, 2);
                sA[mt][rs][lh] = a; sD[mt][rs][lh] = d;
            }

    if (HH == 4) {
        if (lc == 0) {
#pragma unroll
            for (int mt = 0; mt < 2; mt++)
#pragma unroll
                for (int rs = 0; rs < 2; rs++) {
                    int row = rowbase + rg * 32 + mt * 16 + rs * 8 + lr;
                    if (row < M) {
#pragma unroll
                        for (int lh = 0; lh < LH; lh++) {
                            os[row * 4 + cg2 * 2 + lh] = sA[mt][rs][lh];
                            od[row * 4 + cg2 * 2 + lh] = sD[mt][rs][lh];
                        }
                    }
                }
        }
    } else {
        __syncthreads();
        float* sp = smem;
        float* dp = smem + 256;
        if (lc == 0) {
#pragma unroll
            for (int mt = 0; mt < 2; mt++)
#pragma unroll
                for (int rs = 0; rs < 2; rs++) {
                    int lrow = rg * 32 + mt * 16 + rs * 8 + lr;
                    sp[lrow * 2 + cg2] = sA[mt][rs][0];
                    dp[lrow * 2 + cg2] = sD[mt][rs][0];
                }
        }
        __syncthreads();
        if (tid < 128) {
            int row = rowbase + tid;
            if (row < M) {
                os[row] = sp[tid * 2] + sp[tid * 2 + 1];
                od[row] = dp[tid * 2] + dp[tid * 2 + 1];
            }
        }
    }
}

// ---------------------------------------------------------------------------
// CSR aggregation, single sweep (round-13 version).
// ---------------------------------------------------------------------------
__global__ __launch_bounds__(256) void agg128_k(const int* __restrict__ rowptr,
                                                const int* __restrict__ csrc,
                                                const float* __restrict__ feat,
                                                const float* __restrict__ as_,
                                                const float* __restrict__ ad_,
                                                const float* __restrict__ b,
                                                float* __restrict__ out, int N) {
    int gt = blockIdx.x * blockDim.x + threadIdx.x;
    int n = gt >> 5;
    int lane = gt & 31;
    if (n >= N) return;
    int h = lane >> 3;
    float adv = __ldg(ad_ + n * 4 + h);
    int p0 = __ldg(rowptr + n), p1 = __ldg(rowptr + n + 1);

    float den = 0.f;
    float4 acc = make_float4(0.f, 0.f, 0.f, 0.f);
    for (int i = p0; i < p1; i++) {
        int s = __ldg(csrc + i);
        float4 f = __ldg(reinterpret_cast<const float4*>(feat) + (size_t)s * 32 + lane);
        float v = __ldg(as_ + s * 4 + h) + adv;
        v = v > 0.f ? v : 0.2f * v;
        float ex = __expf(v);
        den += ex;
        acc.x += ex * f.x; acc.y += ex * f.y;
        acc.z += ex * f.z; acc.w += ex * f.w;
    }

    float w = 1.f / (den + 1e-16f);
    float4 bb = *reinterpret_cast<const float4*>(b + lane * 4);
    float4 o;
    o.x = fmaxf(acc.x * w + bb.x, 0.f);
    o.y = fmaxf(acc.y * w + bb.y, 0.f);
    o.z = fmaxf(acc.z * w + bb.z, 0.f);
    o.w = fmaxf(acc.w * w + bb.w, 0.f);
    reinterpret_cast<float4*>(out)[(size_t)n * 32 + lane] = o;
}

__global__ __launch_bounds__(256) void agg64_k(const int* __restrict__ rowptr,
                                               const int* __restrict__ csrc,
                                               const float* __restrict__ feat,
                                               const float* __restrict__ as_,
                                               const float* __restrict__ ad_,
                                               const float* __restrict__ b,
                                               float* __restrict__ out, int N) {
    int gt = blockIdx.x * blockDim.x + threadIdx.x;
    int n = gt >> 5;
    int lane = gt & 31;
    if (n >= N) return;
    float adv = __ldg(ad_ + n);
    int p0 = __ldg(rowptr + n), p1 = __ldg(rowptr + n + 1);

    float den = 0.f;
    float2 acc = make_float2(0.f, 0.f);
    for (int i = p0; i < p1; i++) {
        int s = __ldg(csrc + i);
        float2 f = __ldg(reinterpret_cast<const float2*>(feat) + (size_t)s * 32 + lane);
        float v = __ldg(as_ + s) + adv;
        v = v > 0.f ? v : 0.2f * v;
        float ex = __expf(v);
        den += ex;
        acc.x += ex * f.x; acc.y += ex * f.y;
    }

    float w = 1.f / (den + 1e-16f);
    float2 bb = *reinterpret_cast<const float2*>(b + lane * 2);
    float2 o;
    o.x = acc.x * w + bb.x;
    o.y = acc.y * w + bb.y;
    reinterpret_cast<float2*>(out)[(size_t)n * 32 + lane] = o;
}

// ---------------------------------------------------------------------------
extern "C" void kernel_launch(void* const* d_in, const int* in_sizes, int n_in,
                              void* d_out, int out_size) {
    const float* x   = (const float*)d_in[0];
    const void*  ei  = d_in[1];
    const float* W0  = (const float*)d_in[2];
    const float* as0 = (const float*)d_in[3];
    const float* ad0 = (const float*)d_in[4];
    const float* b0  = (const float*)d_in[5];
    const float* W1  = (const float*)d_in[6];
    const float* as1 = (const float*)d_in[7];
    const float* ad1 = (const float*)d_in[8];
    const float* b1  = (const float*)d_in[9];
    const float* W2  = (const float*)d_in[10];
    const float* as2 = (const float*)d_in[11];
    const float* ad2 = (const float*)d_in[12];
    const float* b2  = (const float*)d_in[13];
    float* out = (float*)d_out;

    int N = in_sizes[0] / 128;
    int E = in_sizes[1] / 2;
    int ET = E + N;

    float *feat, *inb, *asb, *adb;
    int *srcp, *dstp, *csrc, *cnt, *fill, *rowptr, *bsum;
    cudaGetSymbolAddress((void**)&feat,   g_feat);
    cudaGetSymbolAddress((void**)&inb,    g_in);
    cudaGetSymbolAddress((void**)&asb,    g_as);
    cudaGetSymbolAddress((void**)&adb,    g_ad);
    cudaGetSymbolAddress((void**)&srcp,   g_src);
    cudaGetSymbolAddress((void**)&dstp,   g_dst);
    cudaGetSymbolAddress((void**)&csrc,   g_csrc);
    cudaGetSymbolAddress((void**)&cnt,    g_cnt);
    cudaGetSymbolAddress((void**)&fill,   g_fill);
    cudaGetSymbolAddress((void**)&rowptr, g_rowptr);
    cudaGetSymbolAddress((void**)&bsum,   g_bsum);

    const int TB = 256;
    int gemmGrid = (N + 127) / 128;
    int aggGrid = ((long)N * 32 + TB - 1) / TB;
    int nchunk = (N + 1023) / 1024;

    const int SM128 = (128 * 68 + 64 * 132) * 4;   // 68608 B
    const int SM64  = (128 * 68 + 64 * 68) * 4;    // 52224 B
    cudaFuncSetAttribute(gemm_tc<128, 4, 1>, cudaFuncAttributeMaxDynamicSharedMemorySize, SM128);
    cudaFuncSetAttribute(gemm_tc<64, 1, 3>,  cudaFuncAttributeMaxDynamicSharedMemorySize, SM64);

    static cudaStream_t s2 = nullptr;
    static cudaEvent_t evFork = nullptr, evJoin = nullptr;
    if (s2 == nullptr) {
        cudaStreamCreateWithFlags(&s2, cudaStreamNonBlocking);
        cudaEventCreateWithFlags(&evFork, cudaEventDisableTiming);
        cudaEventCreateWithFlags(&evJoin, cudaEventDisableTiming);
    }

    // ---- fork: CSR build on s2, concurrent with layer-0 GEMM ----
    cudaEventRecord(evFork, 0);
    cudaStreamWaitEvent(s2, evFork, 0);

    detect_k<<<1, 1, 0, s2>>>((const unsigned int*)ei);
    zero_k<<<(N + TB - 1) / TB, TB, 0, s2>>>(cnt, fill, N);
    decode_hist_k<<<(ET + TB - 1) / TB, TB, 0, s2>>>(ei, E, ET, srcp, dstp, cnt);
    scan1_k<<<nchunk, 1024, 0, s2>>>(cnt, rowptr, bsum, N);
    scan2_k<<<1, 64, 0, s2>>>(bsum, nchunk, rowptr, N);
    scan3_k<<<(N + TB - 1) / TB, TB, 0, s2>>>(rowptr, bsum, N);
    scatter_k<<<(ET + TB - 1) / TB, TB, 0, s2>>>(srcp, dstp, ET, rowptr, fill, csrc);
    cudaEventRecord(evJoin, s2);

    // ---------------- Layer 0 (1-term tf32 GEMM overlaps CSR build) --------
    gemm_tc<128, 4, 1><<<gemmGrid, TB, SM128>>>(x, W0, feat, as0, ad0, asb, adb, N);
    cudaStreamWaitEvent(0, evJoin, 0);
    agg128_k<<<aggGrid, TB>>>(rowptr, csrc, feat, asb, adb, b0, inb, N);

    // ---------------- Layer 1 (1-term tf32) ----------------
    gemm_tc<128, 4, 1><<<gemmGrid, TB, SM128>>>(inb, W1, feat, as1, ad1, asb, adb, N);
    agg128_k<<<aggGrid, TB>>>(rowptr, csrc, feat, asb, adb, b1, inb, N);

    // ---------------- Layer 2 (3-term, accurate) ----------------
    gemm_tc<64, 1, 3><<<gemmGrid, TB, SM64>>>(inb, W2, feat, as2, ad2, asb, adb, N);
    agg64_k<<<aggGrid, TB>>>(rowptr, csrc, feat, asb, adb, b2, out, N);
}